// round 1
// baseline (speedup 1.0000x reference)
#include <cuda_runtime.h>
#include <math.h>

// Problem constants
#define BB 64
#define TT 256
#define EE 300
#define DD 600          // 2*E
#define HH 512
#define GG 2048         // 4*H
#define LL 9
#define MM (BB*TT)      // 16384

// Output layout (flattened float32 concat of the reference tuple)
#define LOG_OFF 0
#define LEN_OFF (MM*LL)            // 147456
#define LL_OFF  (LEN_OFF + BB)     // 147520
#define TAG_OFF (LL_OFF + BB)      // 147584

// -------- scratch (device globals; no allocation allowed) --------
__device__ float g_x[MM*DD];          // (B*T, 600)
__device__ float g_xz[2][MM*GG];      // per-dir x@Wk + b   (B*T, 2048)
__device__ float g_h[2][MM*HH];       // per-dir hidden states (b,t,h)
__device__ float g_c[2][BB*HH];       // per-dir cell state
__device__ int   g_lens[BB];

__device__ __forceinline__ float sigf(float x){ return 1.f/(1.f+expf(-x)); }

// ---------------- embedding gather ----------------
__global__ void embed_kernel(const int* __restrict__ text, const int* __restrict__ sent,
                             const float* __restrict__ wemb, const float* __restrict__ semb)
{
    int idx = blockIdx.x*blockDim.x + threadIdx.x;
    if (idx >= MM*DD) return;
    int e  = idx % DD;
    int bt = idx / DD;
    float v;
    if (e < EE) v = wemb[(long)text[bt]*EE + e];
    else        v = semb[(long)sent[bt]*EE + (e-EE)];
    g_x[idx] = v;
}

// ---------------- xz = x @ Wk_d + b_d  (both directions) ----------------
// C (M=16384, N=2048) = A (M,600) @ B (600,2048) + bias
#define XBM 128
#define XBN 64
#define XBK 16
__global__ void gemm_xz_kernel(const float* __restrict__ Wk_f, const float* __restrict__ b_f,
                               const float* __restrict__ Wk_b, const float* __restrict__ b_b)
{
    int dir = blockIdx.z;
    const float* Bmat = dir ? Wk_b : Wk_f;
    const float* bias = dir ? b_b  : b_f;
    float* C = g_xz[dir];
    const float* A = g_x;

    __shared__ float As[XBK][XBM+4];
    __shared__ float Bs[XBK][XBN];

    int tid = threadIdx.x;                 // 256
    int m0 = blockIdx.x*XBM, n0 = blockIdx.y*XBN;
    int ty = tid/16, tx = tid%16;          // compute mapping: rows ty*8.., cols tx*4..

    float acc[8][4];
    #pragma unroll
    for (int i=0;i<8;i++)
        #pragma unroll
        for (int j=0;j<4;j++) acc[i][j]=0.f;

    for (int k0=0;k0<DD;k0+=XBK){
        #pragma unroll
        for (int p=0;p<8;p++){
            int m = tid/16 + p*16;
            int k = tid%16;
            float v = (k0+k < DD) ? A[(long)(m0+m)*DD + k0+k] : 0.f;
            As[k][m] = v;
        }
        #pragma unroll
        for (int p=0;p<4;p++){
            int k = tid/64 + p*4;
            int n = tid%64;
            float v = (k0+k < DD) ? Bmat[(long)(k0+k)*GG + n0+n] : 0.f;
            Bs[k][n] = v;
        }
        __syncthreads();
        #pragma unroll
        for (int kk=0;kk<XBK;kk++){
            float4 a0 = *(const float4*)&As[kk][ty*8];
            float4 a1 = *(const float4*)&As[kk][ty*8+4];
            float4 b0 = *(const float4*)&Bs[kk][tx*4];
            float av[8] = {a0.x,a0.y,a0.z,a0.w,a1.x,a1.y,a1.z,a1.w};
            float bv[4] = {b0.x,b0.y,b0.z,b0.w};
            #pragma unroll
            for (int i=0;i<8;i++)
                #pragma unroll
                for (int j=0;j<4;j++) acc[i][j] += av[i]*bv[j];
        }
        __syncthreads();
    }
    float4 bvec = *(const float4*)&bias[n0+tx*4];
    #pragma unroll
    for (int i=0;i<8;i++){
        float4 o;
        o.x = acc[i][0]+bvec.x; o.y = acc[i][1]+bvec.y;
        o.z = acc[i][2]+bvec.z; o.w = acc[i][3]+bvec.w;
        *(float4*)&C[(long)(m0+ty*8+i)*GG + n0+tx*4] = o;
    }
}

// ---------------- one LSTM step (both directions in one launch) ----------------
// block: 128 threads. grid: (32 unit-tiles of 16, 2 batch-halves of 32, 2 dirs)
// computes z = xz[t] + h_prev @ Wr  for a 32x64 tile (64 cols = 16 units x 4 gates),
// then gate math + state update.
__global__ void lstm_step_kernel(const float* __restrict__ Wr_f, const float* __restrict__ Wr_b, int s)
{
    int ut  = blockIdx.x;       // 0..31 -> u0 = ut*16
    int bh  = blockIdx.y;       // 0..1  -> b0 = bh*32
    int dir = blockIdx.z;
    const float* Wr = dir ? Wr_b : Wr_f;
    int t  = dir ? (TT-1-s) : s;
    int tp = dir ? (t+1)    : (t-1);
    bool first = (s==0);
    int u0 = ut*16, b0 = bh*32;

    __shared__ float HsT[64][36];   // [k][b]
    __shared__ float Ws [64][64];   // [k][c], c = gg*16+uu
    __shared__ float zb [32][64];   // [b][c]

    int tid = threadIdx.x;          // 128
    int ry = tid>>4;                // 0..7  -> rows ry*4..+3
    int cx = tid&15;                // 0..15 -> cols cx*4..+3

    float acc[4][4];
    #pragma unroll
    for (int i=0;i<4;i++)
        #pragma unroll
        for (int j=0;j<4;j++) acc[i][j]=0.f;

    if (!first){
        const float* hprev = g_h[dir];
        for (int k0=0;k0<HH;k0+=64){
            for (int i=tid;i<32*64;i+=128){
                int b = i>>6, k = i&63;
                HsT[k][b] = hprev[((long)(b0+b)*TT + tp)*HH + k0 + k];
            }
            for (int i=tid;i<64*64;i+=128){
                int k = i>>6, c = i&63;
                int gg = c>>4, uu = c&15;
                Ws[k][c] = Wr[(long)(k0+k)*GG + gg*HH + u0+uu];
            }
            __syncthreads();
            #pragma unroll 8
            for (int kk=0;kk<64;kk++){
                float4 a  = *(const float4*)&HsT[kk][ry*4];
                float4 b4 = *(const float4*)&Ws[kk][cx*4];
                float av[4]={a.x,a.y,a.z,a.w};
                float bv[4]={b4.x,b4.y,b4.z,b4.w};
                #pragma unroll
                for (int i=0;i<4;i++)
                    #pragma unroll
                    for (int j=0;j<4;j++) acc[i][j] += av[i]*bv[j];
            }
            __syncthreads();
        }
    }

    // add xz and stash z tile
    {
        const float* xz = g_xz[dir];
        #pragma unroll
        for (int i=0;i<4;i++){
            int b = ry*4+i;
            #pragma unroll
            for (int j=0;j<4;j++){
                int c = cx*4+j;
                int gg = c>>4, uu = c&15;
                zb[b][c] = acc[i][j] + xz[((long)(b0+b)*TT + t)*GG + gg*HH + u0+uu];
            }
        }
    }
    __syncthreads();

    // gates: 32 batches x 16 units
    for (int i=tid;i<32*16;i+=128){
        int b = i>>4, u = i&15;
        float zi = zb[b][ 0+u];
        float zf = zb[b][16+u];
        float zg = zb[b][32+u];
        float zo = zb[b][48+u];
        int gb = b0+b, gu = u0+u;
        float c_old = first ? 0.f : g_c[dir][gb*HH+gu];
        float cn = sigf(zf)*c_old + sigf(zi)*tanhf(zg);
        float hn = sigf(zo)*tanhf(cn);
        g_c[dir][gb*HH+gu] = cn;
        g_h[dir][((long)gb*TT + t)*HH + gu] = hn;
    }
}

// ---------------- logits = [hf|hb] @ Wd + bd ----------------
__global__ void logits_kernel(const float* __restrict__ Wd, const float* __restrict__ bd,
                              float* __restrict__ out)
{
    __shared__ float sW[LL*2*HH];   // transposed: sW[l*1024 + k]
    int tid = threadIdx.x;          // 256
    for (int i=tid;i<LL*2*HH;i+=256){
        int k = i/LL, l = i%LL;
        sW[l*1024 + k] = Wd[i];
    }
    __syncthreads();
    int warp = tid/32, lane = tid%32;
    int rowbase = blockIdx.x*32 + warp*4;
    for (int rr=0;rr<4;rr++){
        int r = rowbase+rr;
        const float* hfp = &g_h[0][(long)r*HH];
        const float* hbp = &g_h[1][(long)r*HH];
        float acc[LL];
        #pragma unroll
        for (int l=0;l<LL;l++) acc[l]=0.f;
        for (int k=lane;k<HH;k+=32){
            float v0 = hfp[k], v1 = hbp[k];
            #pragma unroll
            for (int l=0;l<LL;l++)
                acc[l] += v0*sW[l*1024+k] + v1*sW[l*1024+HH+k];
        }
        #pragma unroll
        for (int l=0;l<LL;l++)
            #pragma unroll
            for (int off=16;off;off>>=1)
                acc[l] += __shfl_down_sync(0xffffffffu, acc[l], off);
        if (lane==0){
            #pragma unroll
            for (int l=0;l<LL;l++)
                out[(long)r*LL + l] = acc[l] + bd[l];
        }
    }
}

// ---------------- text lens ----------------
__global__ void lens_kernel(const int* __restrict__ text, float* __restrict__ outlen)
{
    __shared__ int sred[TT];
    int b = blockIdx.x, tid = threadIdx.x;
    sred[tid] = (text[b*TT+tid] != 0) ? 1 : 0;
    __syncthreads();
    for (int s=TT/2; s; s>>=1){
        if (tid < s) sred[tid] += sred[tid+s];
        __syncthreads();
    }
    if (tid==0){ g_lens[b] = sred[0]; outlen[b] = (float)sred[0]; }
}

// ---------------- CRF log-likelihood ----------------
__global__ void crf_ll_kernel(const float* __restrict__ logits, const int* __restrict__ labels,
                              const float* __restrict__ trans, float* __restrict__ outll)
{
    int b = blockIdx.x, lane = threadIdx.x;   // 32 threads
    __shared__ float tr[LL*LL];
    for (int i=lane;i<LL*LL;i+=32) tr[i]=trans[i];
    __syncwarp();
    int len = g_lens[b];
    const float* lg = logits + (long)b*TT*LL;
    const int* lab = labels + b*TT;

    float un=0.f, bi=0.f;
    for (int t=lane;t<TT;t+=32){
        if (t < len)          un += lg[t*LL + lab[t]];
        if (t >= 1 && t < len) bi += tr[lab[t-1]*LL + lab[t]];
    }
    #pragma unroll
    for (int off=16;off;off>>=1){
        un += __shfl_down_sync(0xffffffffu, un, off);
        bi += __shfl_down_sync(0xffffffffu, bi, off);
    }

    int j = (lane<LL)? lane : 0;
    float alpha = (lane<LL)? lg[lane] : -1e30f;
    for (int t=1;t<TT;t++){
        float lt = (lane<LL)? lg[t*LL+lane] : 0.f;
        float av[LL]; float mx = -1e30f;
        #pragma unroll
        for (int i=0;i<LL;i++){
            float ai = __shfl_sync(0xffffffffu, alpha, i);
            av[i] = ai + tr[i*LL + j];
            mx = fmaxf(mx, av[i]);
        }
        float s = 0.f;
        #pragma unroll
        for (int i=0;i<LL;i++) s += expf(av[i]-mx);
        float nw = logf(s) + mx + lt;
        if (lane<LL && t<len) alpha = nw;
    }
    float mx2 = -1e30f;
    #pragma unroll
    for (int i=0;i<LL;i++) mx2 = fmaxf(mx2, __shfl_sync(0xffffffffu, alpha, i));
    float s2 = 0.f;
    #pragma unroll
    for (int i=0;i<LL;i++) s2 += expf(__shfl_sync(0xffffffffu, alpha, i) - mx2);
    float log_norm = logf(s2) + mx2;
    if (lane==0) outll[b] = un + bi - log_norm;
}

// ---------------- Viterbi decode ----------------
__global__ void viterbi_kernel(const float* __restrict__ logits, const float* __restrict__ trans,
                               float* __restrict__ outtags)
{
    int b = blockIdx.x, lane = threadIdx.x;   // 32 threads
    __shared__ float tr[LL*LL];
    __shared__ unsigned char bp[TT-1][LL];
    for (int i=lane;i<LL*LL;i+=32) tr[i]=trans[i];
    __syncwarp();
    int len = g_lens[b];
    const float* lg = logits + (long)b*TT*LL;

    int j = (lane<LL)? lane : 0;
    float alpha = (lane<LL)? lg[lane] : -1e30f;
    for (int t=1;t<TT;t++){
        float lt = (lane<LL)? lg[t*LL+lane] : 0.f;
        float best = -1e30f; int bidx = 0;
        #pragma unroll
        for (int i=0;i<LL;i++){
            float v = __shfl_sync(0xffffffffu, alpha, i) + tr[i*LL + j];
            if (v > best){ best = v; bidx = i; }
        }
        if (lane<LL){
            bool m = (t < len);
            if (m) alpha = best + lt;
            bp[t-1][lane] = m ? (unsigned char)bidx : (unsigned char)lane;
        }
    }
    __syncwarp();
    int last = 0; float bv = -1e30f;
    #pragma unroll
    for (int i=0;i<LL;i++){
        float v = __shfl_sync(0xffffffffu, alpha, i);
        if (v > bv){ bv = v; last = i; }
    }
    if (lane==0){
        int tag = last;
        outtags[b*TT + TT-1] = (float)tag;
        for (int t=TT-2;t>=0;t--){
            tag = bp[t][tag];
            outtags[b*TT + t] = (float)tag;
        }
    }
}

// ---------------- launch ----------------
extern "C" void kernel_launch(void* const* d_in, const int* in_sizes, int n_in,
                              void* d_out, int out_size)
{
    const int*   text  = (const int*)  d_in[0];
    const int*   sent  = (const int*)  d_in[1];
    const int*   labels= (const int*)  d_in[2];
    const float* wemb  = (const float*)d_in[3];
    const float* semb  = (const float*)d_in[4];
    const float* Wk_f  = (const float*)d_in[5];
    const float* Wr_f  = (const float*)d_in[6];
    const float* b_f   = (const float*)d_in[7];
    const float* Wk_b  = (const float*)d_in[8];
    const float* Wr_b  = (const float*)d_in[9];
    const float* b_b   = (const float*)d_in[10];
    const float* Wd    = (const float*)d_in[11];
    const float* bd    = (const float*)d_in[12];
    const float* trans = (const float*)d_in[13];
    float* out = (float*)d_out;

    embed_kernel<<<(MM*DD + 255)/256, 256>>>(text, sent, wemb, semb);
    gemm_xz_kernel<<<dim3(MM/XBM, GG/XBN, 2), 256>>>(Wk_f, b_f, Wk_b, b_b);
    for (int s=0;s<TT;s++)
        lstm_step_kernel<<<dim3(32,2,2), 128>>>(Wr_f, Wr_b, s);
    logits_kernel<<<MM/32, 256>>>(Wd, bd, out + LOG_OFF);
    lens_kernel<<<BB, TT>>>(text, out + LEN_OFF);
    crf_ll_kernel<<<BB, 32>>>(out + LOG_OFF, labels, trans, out + LL_OFF);
    viterbi_kernel<<<BB, 32>>>(out + LOG_OFF, trans, out + TAG_OFF);
}

// round 3
// speedup vs baseline: 1.4778x; 1.4778x over previous
#include <cuda_runtime.h>
#include <math.h>

typedef unsigned long long u64;

#define BB 64
#define TT 256
#define DD 600
#define HH 512
#define GG 2048
#define LL 9
#define MM (BB*TT)

#define LEN_OFF (MM*LL)
#define LLK_OFF (LEN_OFF + BB)
#define TAG_OFF (LLK_OFF + BB)

// -------- scratch (device globals) --------
__device__ float g_x[(size_t)MM*DD];
__device__ float g_xz[2][(size_t)MM*GG];
__device__ float g_hT[2][TT][HH][BB];               // [dir][t][u][b]
__device__ __align__(16) u64 g_hP[2][2][(HH/2)*BB]; // [phase][dir][kp*64+b]
__device__ int   g_lens[BB];
__device__ unsigned g_cnt;

__device__ __forceinline__ u64 ffma2(u64 a, u64 b, u64 c){
    u64 d; asm("fma.rn.f32x2 %0,%1,%2,%3;" : "=l"(d) : "l"(a), "l"(b), "l"(c)); return d;
}
__device__ __forceinline__ u64 pkf(float lo, float hi){
    u64 d; asm("mov.b64 %0,{%1,%2};" : "=l"(d) : "f"(lo), "f"(hi)); return d;
}
__device__ __forceinline__ float foldu(u64 v){
    float2 f = *reinterpret_cast<float2*>(&v); return f.x + f.y;
}
__device__ __forceinline__ float sigf(float x){ return 1.f/(1.f+expf(-x)); }

// ---------------- embedding gather ----------------
__global__ void embed_kernel(const int* __restrict__ text, const int* __restrict__ sent,
                             const float* __restrict__ wemb, const float* __restrict__ semb)
{
    int idx = blockIdx.x*blockDim.x + threadIdx.x;
    if (idx == 0) g_cnt = 0;
    if (idx >= MM*DD) return;
    int e = idx % DD, bt = idx / DD;
    g_x[idx] = (e < 300) ? wemb[(long)text[bt]*300 + e] : semb[(long)sent[bt]*300 + (e-300)];
}

// ---------------- xz = x @ Wk + b  (f32x2, double-buffered) ----------------
#define GKP 12
#define GCH 25
__global__ void __launch_bounds__(256,2) gemm_xz_kernel(const float* __restrict__ Wk_f, const float* __restrict__ b_f,
                                                        const float* __restrict__ Wk_b, const float* __restrict__ b_b)
{
    __shared__ u64 As2[2][GKP][128];
    __shared__ u64 Bs2[2][GKP][64];

    int tid = threadIdx.x;
    int m0g = blockIdx.x*128;
    int nb  = blockIdx.y;
    const float* Bmat = (nb>=32)? Wk_b : Wk_f;
    const float* bias = (nb>=32)? b_b  : b_f;
    float* C = (nb>=32)? g_xz[1] : g_xz[0];
    int n0 = (nb&31)*64;
    int ty = tid>>4, tx = tid&15;

    u64 acc[8][4];
    #pragma unroll
    for (int i=0;i<8;i++)
        #pragma unroll
        for (int j=0;j<4;j++) acc[i][j]=0ULL;

    float4 pa[3], pb0, pb1;
    int bkp = tid>>4, bng = tid&15;

    // prologue: chunk 0
    #pragma unroll
    for (int r=0;r<3;r++){
        int idx = r*256+tid; int m = idx/6, j = idx%6;
        pa[r] = *(const float4*)&g_x[(long)(m0g+m)*DD + j*4];
    }
    if (tid < 192){
        const float* bp = &Bmat[(long)(2*bkp)*GG + n0 + bng*4];
        pb0 = *(const float4*)bp; pb1 = *(const float4*)(bp + GG);
    }
    #pragma unroll
    for (int r=0;r<3;r++){
        int idx = r*256+tid; int m = idx/6, j = idx%6;
        As2[0][2*j  ][m] = pkf(pa[r].x, pa[r].y);
        As2[0][2*j+1][m] = pkf(pa[r].z, pa[r].w);
    }
    if (tid < 192){
        u64* dst = &Bs2[0][bkp][bng*4];
        dst[0]=pkf(pb0.x,pb1.x); dst[1]=pkf(pb0.y,pb1.y);
        dst[2]=pkf(pb0.z,pb1.z); dst[3]=pkf(pb0.w,pb1.w);
    }
    __syncthreads();

    for (int ch=0; ch<GCH; ch++){
        int cur = ch&1;
        if (ch+1 < GCH){
            int kbase = (ch+1)*24;
            #pragma unroll
            for (int r=0;r<3;r++){
                int idx = r*256+tid; int m = idx/6, j = idx%6;
                pa[r] = *(const float4*)&g_x[(long)(m0g+m)*DD + kbase + j*4];
            }
            if (tid < 192){
                const float* bp = &Bmat[(long)(kbase + 2*bkp)*GG + n0 + bng*4];
                pb0 = *(const float4*)bp; pb1 = *(const float4*)(bp + GG);
            }
        }
        #pragma unroll
        for (int kp=0;kp<GKP;kp++){
            u64 a[8], b[4];
            *(ulonglong2*)&a[0] = *(const ulonglong2*)&As2[cur][kp][ty*8];
            *(ulonglong2*)&a[2] = *(const ulonglong2*)&As2[cur][kp][ty*8+2];
            *(ulonglong2*)&a[4] = *(const ulonglong2*)&As2[cur][kp][ty*8+4];
            *(ulonglong2*)&a[6] = *(const ulonglong2*)&As2[cur][kp][ty*8+6];
            *(ulonglong2*)&b[0] = *(const ulonglong2*)&Bs2[cur][kp][tx*4];
            *(ulonglong2*)&b[2] = *(const ulonglong2*)&Bs2[cur][kp][tx*4+2];
            #pragma unroll
            for (int i=0;i<8;i++)
                #pragma unroll
                for (int j=0;j<4;j++) acc[i][j] = ffma2(a[i], b[j], acc[i][j]);
        }
        if (ch+1 < GCH){
            int nb2 = (ch+1)&1;
            #pragma unroll
            for (int r=0;r<3;r++){
                int idx = r*256+tid; int m = idx/6, j = idx%6;
                As2[nb2][2*j  ][m] = pkf(pa[r].x, pa[r].y);
                As2[nb2][2*j+1][m] = pkf(pa[r].z, pa[r].w);
            }
            if (tid < 192){
                u64* dst = &Bs2[nb2][bkp][bng*4];
                dst[0]=pkf(pb0.x,pb1.x); dst[1]=pkf(pb0.y,pb1.y);
                dst[2]=pkf(pb0.z,pb1.z); dst[3]=pkf(pb0.w,pb1.w);
            }
        }
        __syncthreads();
    }

    float4 bvec = *(const float4*)&bias[n0 + tx*4];
    #pragma unroll
    for (int i=0;i<8;i++){
        float4 o;
        o.x = foldu(acc[i][0]) + bvec.x;
        o.y = foldu(acc[i][1]) + bvec.y;
        o.z = foldu(acc[i][2]) + bvec.z;
        o.w = foldu(acc[i][3]) + bvec.w;
        *(float4*)&C[(long)(m0g + ty*8 + i)*GG + n0 + tx*4] = o;
    }
}

// ---------------- persistent bidirectional LSTM ----------------
// 128 blocks x 128 threads. Block (dir = bid>>6, ub = bid&63): units u0 = ub*8.
// smem: Ws2 [256kp][32c] (64KB) + Hs2 2x[32kp][64b] (32KB) + Xs 2048 f (8KB)
#define LSTM_SMEM ((8192+4096)*8 + 2048*4)
__global__ void __launch_bounds__(128,1) lstm_persistent(const float* __restrict__ Wr_f,
                                                         const float* __restrict__ Wr_b)
{
    extern __shared__ u64 dyn[];
    u64*   Ws2 = dyn;
    u64*   Hs2 = dyn + 8192;
    float* Xs  = (float*)(dyn + 8192 + 4096);

    int tid = threadIdx.x, bid = blockIdx.x;
    int dir = bid>>6, ub = bid&63, u0 = ub*8;
    const float* Wr = dir ? Wr_b : Wr_f;
    const float* xz = g_xz[dir];

    // stage weights k-paired: Ws2[kp*32+c], c = g*8+uu
    for (int i=tid; i<8192; i+=128){
        int kp = i>>5, c = i&31, g = c>>3, uu = c&7;
        int col = g*HH + u0 + uu;
        Ws2[i] = pkf(Wr[(long)(2*kp)*GG + col], Wr[(long)(2*kp+1)*GG + col]);
    }
    float2 c0s = {0.f,0.f}, c1s = {0.f,0.f};
    int b0 = (tid>>3)*4, cc0 = (tid&7)*4;
    __syncthreads();

    for (int s=0; s<TT; s++){
        int t = dir ? (TT-1-s) : s;
        int ph = s&1;

        // load xz tile (Xs[b*32+c])
        #pragma unroll
        for (int j=0;j<16;j++){
            int idx = j*128 + tid;
            int b = idx>>5, c = idx&31, g = c>>3, uu = c&7;
            Xs[idx] = xz[((long)b*TT + t)*GG + g*HH + u0 + uu];
        }

        u64 acc[4][4];
        #pragma unroll
        for (int i=0;i<4;i++)
            #pragma unroll
            for (int j=0;j<4;j++) acc[i][j]=0ULL;

        if (s){
            const uint4* hsrc = (const uint4*)&g_hP[ph^1][dir][0];
            uint4 pf[8];
            #pragma unroll
            for (int j=0;j<8;j++) pf[j] = __ldcg(&hsrc[j*128 + tid]);
            __syncthreads();
            #pragma unroll
            for (int j=0;j<8;j++) *(uint4*)&Hs2[(j*128+tid)*2] = pf[j];
            __syncthreads();

            for (int ch=0; ch<8; ch++){
                if (ch<7){
                    #pragma unroll
                    for (int j=0;j<8;j++) pf[j] = __ldcg(&hsrc[(ch+1)*1024 + j*128 + tid]);
                }
                const u64* Hb = Hs2 + (ch&1)*2048;
                const u64* Wb = Ws2 + ch*32*32;
                #pragma unroll 16
                for (int kk=0;kk<32;kk++){
                    u64 hv[4], wv[4];
                    *(ulonglong2*)&hv[0] = *(const ulonglong2*)&Hb[kk*64 + b0];
                    *(ulonglong2*)&hv[2] = *(const ulonglong2*)&Hb[kk*64 + b0 + 2];
                    *(ulonglong2*)&wv[0] = *(const ulonglong2*)&Wb[kk*32 + cc0];
                    *(ulonglong2*)&wv[2] = *(const ulonglong2*)&Wb[kk*32 + cc0 + 2];
                    #pragma unroll
                    for (int i=0;i<4;i++)
                        #pragma unroll
                        for (int j=0;j<4;j++) acc[i][j] = ffma2(hv[i], wv[j], acc[i][j]);
                }
                if (ch<7){
                    #pragma unroll
                    for (int j=0;j<8;j++) *(uint4*)&Hs2[((ch+1)&1)*2048 + (j*128+tid)*2] = pf[j];
                }
                __syncthreads();
            }
        } else {
            __syncthreads();
        }

        // z = fold(acc) + xz, in-place in Xs
        #pragma unroll
        for (int i=0;i<4;i++)
            #pragma unroll
            for (int j=0;j<4;j++){
                int idx = (b0+i)*32 + cc0 + j;
                Xs[idx] = foldu(acc[i][j]) + Xs[idx];
            }
        __syncthreads();

        // gates: 2 slots per thread, each slot = (kpl, b) -> units u0+2kpl, u0+2kpl+1
        #pragma unroll
        for (int sl=0; sl<2; sl++){
            int slot = tid + sl*128;
            int kpl = slot>>6, b = slot&63;
            float2 cs = sl ? c1s : c0s;
            int base = b*32 + 2*kpl;
            float zi0 = Xs[base+ 0], zi1 = Xs[base+ 1];
            float zf0 = Xs[base+ 8], zf1 = Xs[base+ 9];
            float zg0 = Xs[base+16], zg1 = Xs[base+17];
            float zo0 = Xs[base+24], zo1 = Xs[base+25];
            float cn0 = sigf(zf0)*cs.x + sigf(zi0)*tanhf(zg0);
            float cn1 = sigf(zf1)*cs.y + sigf(zi1)*tanhf(zg1);
            float h0 = sigf(zo0)*tanhf(cn0);
            float h1 = sigf(zo1)*tanhf(cn1);
            if (sl){ c1s.x=cn0; c1s.y=cn1; } else { c0s.x=cn0; c0s.y=cn1; }
            g_hP[ph][dir][(ub*4 + kpl)*64 + b] = pkf(h0, h1);
            int ug = u0 + 2*kpl;
            g_hT[dir][t][ug  ][b] = h0;
            g_hT[dir][t][ug+1][b] = h1;
        }

        if (s < TT-1){
            __threadfence();
            __syncthreads();
            if (tid==0){
                atomicAdd(&g_cnt, 1u);
                unsigned tgt = 128u*(unsigned)(s+1);
                while (*(volatile unsigned*)&g_cnt < tgt) __nanosleep(32);
            }
            __syncthreads();
        }
    }
}

// ---------------- logits = [hf|hb] @ Wd + bd ----------------
__global__ void logits_kernel(const float* __restrict__ Wd, const float* __restrict__ bd,
                              float* __restrict__ out)
{
    __shared__ float sW[2*HH*LL];
    int tid = threadIdx.x;
    for (int i=tid;i<2*HH*LL;i+=256) sW[i] = Wd[i];
    __syncthreads();
    int t = blockIdx.x*4 + (tid>>6);
    int b = tid&63;
    float acc[LL];
    #pragma unroll
    for (int l=0;l<LL;l++) acc[l]=0.f;
    for (int u=0;u<HH;u++){
        float hf = g_hT[0][t][u][b];
        float hb = g_hT[1][t][u][b];
        #pragma unroll
        for (int l=0;l<LL;l++)
            acc[l] += hf*sW[u*LL+l] + hb*sW[(HH+u)*LL+l];
    }
    #pragma unroll
    for (int l=0;l<LL;l++)
        out[((long)b*TT + t)*LL + l] = acc[l] + bd[l];
}

// ---------------- text lens ----------------
__global__ void lens_kernel(const int* __restrict__ text, float* __restrict__ outlen)
{
    __shared__ int sred[TT];
    int b = blockIdx.x, tid = threadIdx.x;
    sred[tid] = (text[b*TT+tid] != 0) ? 1 : 0;
    __syncthreads();
    for (int s=TT/2; s; s>>=1){
        if (tid < s) sred[tid] += sred[tid+s];
        __syncthreads();
    }
    if (tid==0){ g_lens[b] = sred[0]; outlen[b] = (float)sred[0]; }
}

// ---------------- CRF log-likelihood ----------------
__global__ void crf_ll_kernel(const float* __restrict__ logits, const int* __restrict__ labels,
                              const float* __restrict__ trans, float* __restrict__ outll)
{
    int b = blockIdx.x, lane = threadIdx.x;
    __shared__ float tr[LL*LL];
    for (int i=lane;i<LL*LL;i+=32) tr[i]=trans[i];
    __syncwarp();
    int len = g_lens[b];
    const float* lg = logits + (long)b*TT*LL;
    const int* lab = labels + b*TT;

    float un=0.f, bi=0.f;
    for (int t=lane;t<TT;t+=32){
        if (t < len)           un += lg[t*LL + lab[t]];
        if (t >= 1 && t < len) bi += tr[lab[t-1]*LL + lab[t]];
    }
    #pragma unroll
    for (int off=16;off;off>>=1){
        un += __shfl_down_sync(0xffffffffu, un, off);
        bi += __shfl_down_sync(0xffffffffu, bi, off);
    }

    int j = (lane<LL)? lane : 0;
    float alpha = (lane<LL)? lg[lane] : -1e30f;
    for (int t=1;t<TT;t++){
        float lt = (lane<LL)? lg[t*LL+lane] : 0.f;
        float av[LL]; float mx = -1e30f;
        #pragma unroll
        for (int i=0;i<LL;i++){
            float ai = __shfl_sync(0xffffffffu, alpha, i);
            av[i] = ai + tr[i*LL + j];
            mx = fmaxf(mx, av[i]);
        }
        float ssum = 0.f;
        #pragma unroll
        for (int i=0;i<LL;i++) ssum += expf(av[i]-mx);
        float nw = logf(ssum) + mx + lt;
        if (lane<LL && t<len) alpha = nw;
    }
    float mx2 = -1e30f;
    #pragma unroll
    for (int i=0;i<LL;i++) mx2 = fmaxf(mx2, __shfl_sync(0xffffffffu, alpha, i));
    float s2 = 0.f;
    #pragma unroll
    for (int i=0;i<LL;i++) s2 += expf(__shfl_sync(0xffffffffu, alpha, i) - mx2);
    float log_norm = logf(s2) + mx2;
    if (lane==0) outll[b] = un + bi - log_norm;
}

// ---------------- Viterbi decode ----------------
__global__ void viterbi_kernel(const float* __restrict__ logits, const float* __restrict__ trans,
                               float* __restrict__ outtags)
{
    int b = blockIdx.x, lane = threadIdx.x;
    __shared__ float tr[LL*LL];
    __shared__ unsigned char bp[TT-1][LL];
    for (int i=lane;i<LL*LL;i+=32) tr[i]=trans[i];
    __syncwarp();
    int len = g_lens[b];
    const float* lg = logits + (long)b*TT*LL;

    float alpha = (lane<LL)? lg[lane] : -1e30f;
    int j = (lane<LL)? lane : 0;
    for (int t=1;t<TT;t++){
        float lt = (lane<LL)? lg[t*LL+lane] : 0.f;
        float best = -1e30f; int bidx = 0;
        #pragma unroll
        for (int i=0;i<LL;i++){
            float v = __shfl_sync(0xffffffffu, alpha, i) + tr[i*LL + j];
            if (v > best){ best = v; bidx = i; }
        }
        if (lane<LL){
            bool m = (t < len);
            if (m) alpha = best + lt;
            bp[t-1][lane] = m ? (unsigned char)bidx : (unsigned char)lane;
        }
    }
    __syncwarp();
    int last = 0; float bv = -1e30f;
    #pragma unroll
    for (int i=0;i<LL;i++){
        float v = __shfl_sync(0xffffffffu, alpha, i);
        if (v > bv){ bv = v; last = i; }
    }
    if (lane==0){
        int tag = last;
        outtags[b*TT + TT-1] = (float)tag;
        for (int t=TT-2;t>=0;t--){
            tag = bp[t][tag];
            outtags[b*TT + t] = (float)tag;
        }
    }
}

// ---------------- launch ----------------
extern "C" void kernel_launch(void* const* d_in, const int* in_sizes, int n_in,
                              void* d_out, int out_size)
{
    const int*   text  = (const int*)  d_in[0];
    const int*   sent  = (const int*)  d_in[1];
    const int*   labels= (const int*)  d_in[2];
    const float* wemb  = (const float*)d_in[3];
    const float* semb  = (const float*)d_in[4];
    const float* Wk_f  = (const float*)d_in[5];
    const float* Wr_f  = (const float*)d_in[6];
    const float* b_f   = (const float*)d_in[7];
    const float* Wk_b  = (const float*)d_in[8];
    const float* Wr_b  = (const float*)d_in[9];
    const float* b_b   = (const float*)d_in[10];
    const float* Wd    = (const float*)d_in[11];
    const float* bd    = (const float*)d_in[12];
    const float* trans = (const float*)d_in[13];
    float* out = (float*)d_out;

    cudaFuncSetAttribute(lstm_persistent, cudaFuncAttributeMaxDynamicSharedMemorySize, LSTM_SMEM);

    embed_kernel<<<(MM*DD + 255)/256, 256>>>(text, sent, wemb, semb);
    gemm_xz_kernel<<<dim3(128, 64), 256>>>(Wk_f, b_f, Wk_b, b_b);
    lstm_persistent<<<128, 128, LSTM_SMEM>>>(Wr_f, Wr_b);
    logits_kernel<<<64, 256>>>(Wd, bd, out);
    lens_kernel<<<BB, TT>>>(text, out + LEN_OFF);
    crf_ll_kernel<<<BB, 32>>>(out, labels, trans, out + LLK_OFF);
    viterbi_kernel<<<BB, 32>>>(out, trans, out + TAG_OFF);
}

// round 4
// speedup vs baseline: 1.8875x; 1.2773x over previous
#include <cuda_runtime.h>
#include <math.h>

typedef unsigned long long u64;

#define BB 64
#define TT 256
#define DD 600
#define HH 512
#define GG 2048
#define LL 9
#define MM (BB*TT)

#define LEN_OFF (MM*LL)
#define LLK_OFF (LEN_OFF + BB)
#define TAG_OFF (LLK_OFF + BB)

// -------- scratch (device globals) --------
__device__ float g_x[(size_t)MM*DD];
__device__ float g_xz[2][(size_t)MM*GG];
__device__ float g_hT[2][TT][HH][BB];               // [dir][t][u][b]
__device__ __align__(16) u64 g_hP[2][2][(HH/2)*BB]; // [phase][dir][kp*64+b]
__device__ int   g_lens[BB];
__device__ unsigned g_cnt2[2];

__device__ __forceinline__ u64 ffma2(u64 a, u64 b, u64 c){
    u64 d; asm("fma.rn.f32x2 %0,%1,%2,%3;" : "=l"(d) : "l"(a), "l"(b), "l"(c)); return d;
}
__device__ __forceinline__ u64 pkf(float lo, float hi){
    u64 d; asm("mov.b64 %0,{%1,%2};" : "=l"(d) : "f"(lo), "f"(hi)); return d;
}
__device__ __forceinline__ float foldu(u64 v){
    float2 f = *reinterpret_cast<float2*>(&v); return f.x + f.y;
}
__device__ __forceinline__ float sigf(float x){ return 1.f/(1.f+expf(-x)); }
__device__ __forceinline__ unsigned f2tf(float f){
    unsigned r; asm("cvt.rna.tf32.f32 %0,%1;" : "=r"(r) : "f"(f)); return r;
}
__device__ __forceinline__ void mma8(float* d, const unsigned* a, const unsigned* b){
    asm("mma.sync.aligned.m16n8k8.row.col.f32.tf32.tf32.f32 "
        "{%0,%1,%2,%3},{%4,%5,%6,%7},{%8,%9},{%0,%1,%2,%3};"
        : "+f"(d[0]),"+f"(d[1]),"+f"(d[2]),"+f"(d[3])
        : "r"(a[0]),"r"(a[1]),"r"(a[2]),"r"(a[3]),"r"(b[0]),"r"(b[1]));
}

// ---------------- embedding gather ----------------
__global__ void embed_kernel(const int* __restrict__ text, const int* __restrict__ sent,
                             const float* __restrict__ wemb, const float* __restrict__ semb)
{
    int idx = blockIdx.x*blockDim.x + threadIdx.x;
    if (idx == 0){ g_cnt2[0] = 0; g_cnt2[1] = 0; }
    if (idx >= MM*DD) return;
    int e = idx % DD, bt = idx / DD;
    g_x[idx] = (e < 300) ? wemb[(long)text[bt]*300 + e] : semb[(long)sent[bt]*300 + (e-300)];
}

// ---------------- xz = x @ Wk + b  (TF32 mma.sync, double-buffered) ----------------
// block 256 thr (8 warps), tile 128m x 64n, K-chunks of 24 (3 k8 steps), 25 chunks.
// As[m][k] stride 28 (bank-clean frags), Ws[k][n] stride 72 (bank-clean frags).
#define AST 28
#define WST 72
__global__ void __launch_bounds__(256,2) gemm_xz_kernel(const float* __restrict__ Wk_f, const float* __restrict__ b_f,
                                                        const float* __restrict__ Wk_b, const float* __restrict__ b_b)
{
    __shared__ unsigned As[2][128*AST];
    __shared__ unsigned Ws[2][24*WST];

    int tid = threadIdx.x;
    int warp = tid>>5, lane = tid&31;
    int g = lane>>2, tig = lane&3;
    int m0g = blockIdx.x*128;
    int nb  = blockIdx.y;
    const float* Bmat = (nb>=32)? Wk_b : Wk_f;
    const float* bias = (nb>=32)? b_b  : b_f;
    float* C = (nb>=32)? g_xz[1] : g_xz[0];
    int n0g = (nb&31)*64;
    int wm = (warp>>1)*32;   // warp m offset (0,32,64,96)
    int wn = (warp&1)*32;    // warp n offset (0,32)

    float acc[2][4][4];
    #pragma unroll
    for (int mt=0;mt<2;mt++)
        #pragma unroll
        for (int nt=0;nt<4;nt++)
            #pragma unroll
            for (int r=0;r<4;r++) acc[mt][nt][r]=0.f;

    // staging indices
    int arow = tid>>1, acb = (tid&1)*12;          // A: 3 float4 per thread
    int wi0 = tid*2;                              // W: threads<192, 2 float4 each

    float4 pa[3], pw[2];
    // prologue: chunk 0 load
    #pragma unroll
    for (int j=0;j<3;j++)
        pa[j] = *(const float4*)&g_x[(long)(m0g+arow)*DD + acb + 4*j];
    if (tid < 192){
        #pragma unroll
        for (int q=0;q<2;q++){
            int i = wi0+q; int k = i>>4, nq = i&15;
            pw[q] = *(const float4*)&Bmat[(long)k*GG + n0g + nq*4];
        }
    }
    // store chunk 0
    #pragma unroll
    for (int j=0;j<3;j++){
        unsigned* d = &As[0][arow*AST + acb + 4*j];
        d[0]=f2tf(pa[j].x); d[1]=f2tf(pa[j].y); d[2]=f2tf(pa[j].z); d[3]=f2tf(pa[j].w);
    }
    if (tid < 192){
        #pragma unroll
        for (int q=0;q<2;q++){
            int i = wi0+q; int k = i>>4, nq = i&15;
            unsigned* d = &Ws[0][k*WST + nq*4];
            d[0]=f2tf(pw[q].x); d[1]=f2tf(pw[q].y); d[2]=f2tf(pw[q].z); d[3]=f2tf(pw[q].w);
        }
    }
    __syncthreads();

    for (int ch=0; ch<25; ch++){
        int cur = ch&1;
        if (ch < 24){
            int kb = (ch+1)*24;
            #pragma unroll
            for (int j=0;j<3;j++)
                pa[j] = *(const float4*)&g_x[(long)(m0g+arow)*DD + kb + acb + 4*j];
            if (tid < 192){
                #pragma unroll
                for (int q=0;q<2;q++){
                    int i = wi0+q; int k = i>>4, nq = i&15;
                    pw[q] = *(const float4*)&Bmat[(long)(kb+k)*GG + n0g + nq*4];
                }
            }
        }
        const unsigned* Ab = &As[cur][0];
        const unsigned* Wb = &Ws[cur][0];
        #pragma unroll
        for (int ks=0;ks<3;ks++){
            int kb = ks*8;
            unsigned a[2][4], b[4][2];
            #pragma unroll
            for (int mt=0;mt<2;mt++){
                int r0 = wm + mt*16;
                a[mt][0] = Ab[(r0+g  )*AST + kb+tig  ];
                a[mt][1] = Ab[(r0+g+8)*AST + kb+tig  ];
                a[mt][2] = Ab[(r0+g  )*AST + kb+tig+4];
                a[mt][3] = Ab[(r0+g+8)*AST + kb+tig+4];
            }
            #pragma unroll
            for (int nt=0;nt<4;nt++){
                int c0 = wn + nt*8 + g;
                b[nt][0] = Wb[(kb+tig  )*WST + c0];
                b[nt][1] = Wb[(kb+tig+4)*WST + c0];
            }
            #pragma unroll
            for (int mt=0;mt<2;mt++)
                #pragma unroll
                for (int nt=0;nt<4;nt++)
                    mma8(acc[mt][nt], a[mt], b[nt]);
        }
        if (ch < 24){
            int nxt = (ch+1)&1;
            #pragma unroll
            for (int j=0;j<3;j++){
                unsigned* d = &As[nxt][arow*AST + acb + 4*j];
                d[0]=f2tf(pa[j].x); d[1]=f2tf(pa[j].y); d[2]=f2tf(pa[j].z); d[3]=f2tf(pa[j].w);
            }
            if (tid < 192){
                #pragma unroll
                for (int q=0;q<2;q++){
                    int i = wi0+q; int k = i>>4, nq = i&15;
                    unsigned* d = &Ws[nxt][k*WST + nq*4];
                    d[0]=f2tf(pw[q].x); d[1]=f2tf(pw[q].y); d[2]=f2tf(pw[q].z); d[3]=f2tf(pw[q].w);
                }
            }
        }
        __syncthreads();
    }

    // epilogue: D + bias
    #pragma unroll
    for (int mt=0;mt<2;mt++){
        int row0 = m0g + wm + mt*16 + g;
        #pragma unroll
        for (int nt=0;nt<4;nt++){
            int col = n0g + wn + nt*8 + 2*tig;
            float b0 = bias[col], b1 = bias[col+1];
            float2 o0 = {acc[mt][nt][0]+b0, acc[mt][nt][1]+b1};
            float2 o1 = {acc[mt][nt][2]+b0, acc[mt][nt][3]+b1};
            *(float2*)&C[(long)row0*GG + col]     = o0;
            *(float2*)&C[(long)(row0+8)*GG + col] = o1;
        }
    }
}

// ---------------- persistent bidirectional LSTM (f32x2) ----------------
#define LSTM_SMEM ((8192+4096)*8 + 2048*4)
__global__ void __launch_bounds__(128,1) lstm_persistent(const float* __restrict__ Wr_f,
                                                         const float* __restrict__ Wr_b)
{
    extern __shared__ u64 dyn[];
    u64*   Ws2 = dyn;
    u64*   Hs2 = dyn + 8192;
    float* Xs  = (float*)(dyn + 8192 + 4096);

    int tid = threadIdx.x, bid = blockIdx.x;
    int dir = bid>>6, ub = bid&63, u0 = ub*8;
    const float* Wr = dir ? Wr_b : Wr_f;
    const float* xz = g_xz[dir];

    for (int i=tid; i<8192; i+=128){
        int kp = i>>5, c = i&31, g = c>>3, uu = c&7;
        int col = g*HH + u0 + uu;
        Ws2[i] = pkf(Wr[(long)(2*kp)*GG + col], Wr[(long)(2*kp+1)*GG + col]);
    }
    float2 c0s = {0.f,0.f}, c1s = {0.f,0.f};
    int b0 = (tid>>3)*4, cc0 = (tid&7)*4;
    __syncthreads();

    for (int s=0; s<TT; s++){
        int t = dir ? (TT-1-s) : s;
        int ph = s&1;

        #pragma unroll
        for (int j=0;j<16;j++){
            int idx = j*128 + tid;
            int b = idx>>5, c = idx&31, g = c>>3, uu = c&7;
            Xs[idx] = xz[((long)b*TT + t)*GG + g*HH + u0 + uu];
        }

        u64 acc[4][4];
        #pragma unroll
        for (int i=0;i<4;i++)
            #pragma unroll
            for (int j=0;j<4;j++) acc[i][j]=0ULL;

        if (s){
            const uint4* hsrc = (const uint4*)&g_hP[ph^1][dir][0];
            uint4 pf[8];
            #pragma unroll
            for (int j=0;j<8;j++) pf[j] = __ldcg(&hsrc[j*128 + tid]);
            __syncthreads();
            #pragma unroll
            for (int j=0;j<8;j++) *(uint4*)&Hs2[(j*128+tid)*2] = pf[j];
            __syncthreads();

            for (int ch=0; ch<8; ch++){
                if (ch<7){
                    #pragma unroll
                    for (int j=0;j<8;j++) pf[j] = __ldcg(&hsrc[(ch+1)*1024 + j*128 + tid]);
                }
                const u64* Hb = Hs2 + (ch&1)*2048;
                const u64* Wb = Ws2 + ch*32*32;
                #pragma unroll 16
                for (int kk=0;kk<32;kk++){
                    u64 hv[4], wv[4];
                    *(ulonglong2*)&hv[0] = *(const ulonglong2*)&Hb[kk*64 + b0];
                    *(ulonglong2*)&hv[2] = *(const ulonglong2*)&Hb[kk*64 + b0 + 2];
                    *(ulonglong2*)&wv[0] = *(const ulonglong2*)&Wb[kk*32 + cc0];
                    *(ulonglong2*)&wv[2] = *(const ulonglong2*)&Wb[kk*32 + cc0 + 2];
                    #pragma unroll
                    for (int i=0;i<4;i++)
                        #pragma unroll
                        for (int j=0;j<4;j++) acc[i][j] = ffma2(hv[i], wv[j], acc[i][j]);
                }
                if (ch<7){
                    #pragma unroll
                    for (int j=0;j<8;j++) *(uint4*)&Hs2[((ch+1)&1)*2048 + (j*128+tid)*2] = pf[j];
                }
                __syncthreads();
            }
        } else {
            __syncthreads();
        }

        #pragma unroll
        for (int i=0;i<4;i++)
            #pragma unroll
            for (int j=0;j<4;j++){
                int idx = (b0+i)*32 + cc0 + j;
                Xs[idx] = foldu(acc[i][j]) + Xs[idx];
            }
        __syncthreads();

        #pragma unroll
        for (int sl=0; sl<2; sl++){
            int slot = tid + sl*128;
            int kpl = slot>>6, b = slot&63;
            float2 cs = sl ? c1s : c0s;
            int base = b*32 + 2*kpl;
            float zi0 = Xs[base+ 0], zi1 = Xs[base+ 1];
            float zf0 = Xs[base+ 8], zf1 = Xs[base+ 9];
            float zg0 = Xs[base+16], zg1 = Xs[base+17];
            float zo0 = Xs[base+24], zo1 = Xs[base+25];
            float cn0 = sigf(zf0)*cs.x + sigf(zi0)*tanhf(zg0);
            float cn1 = sigf(zf1)*cs.y + sigf(zi1)*tanhf(zg1);
            float h0 = sigf(zo0)*tanhf(cn0);
            float h1 = sigf(zo1)*tanhf(cn1);
            if (sl){ c1s.x=cn0; c1s.y=cn1; } else { c0s.x=cn0; c0s.y=cn1; }
            g_hP[ph][dir][(ub*4 + kpl)*64 + b] = pkf(h0, h1);
            int ug = u0 + 2*kpl;
            g_hT[dir][t][ug  ][b] = h0;
            g_hT[dir][t][ug+1][b] = h1;
        }

        if (s < TT-1){
            __threadfence();
            __syncthreads();
            if (tid==0){
                atomicAdd(&g_cnt2[dir], 1u);
                unsigned tgt = 64u*(unsigned)(s+1);
                while (*(volatile unsigned*)&g_cnt2[dir] < tgt) __nanosleep(32);
            }
            __syncthreads();
        }
    }
}

// ---------------- logits = [hf|hb] @ Wd + bd ----------------
// grid 256 (one t per block), block 64 (one b per thread)
__global__ void logits_kernel(const float* __restrict__ Wd, const float* __restrict__ bd,
                              float* __restrict__ out)
{
    __shared__ float sW[2*HH*LL];
    int t = blockIdx.x, b = threadIdx.x;
    for (int i=b;i<2*HH*LL;i+=64) sW[i] = Wd[i];
    __syncthreads();
    float acc[LL];
    #pragma unroll
    for (int l=0;l<LL;l++) acc[l]=0.f;
    const float* hf = &g_hT[0][t][0][0];
    const float* hb = &g_hT[1][t][0][0];
    #pragma unroll 8
    for (int u=0;u<HH;u++){
        float vf = hf[u*BB + b];
        float vb = hb[u*BB + b];
        #pragma unroll
        for (int l=0;l<LL;l++)
            acc[l] += vf*sW[u*LL+l] + vb*sW[(HH+u)*LL+l];
    }
    #pragma unroll
    for (int l=0;l<LL;l++)
        out[((long)b*TT + t)*LL + l] = acc[l] + bd[l];
}

// ---------------- text lens ----------------
__global__ void lens_kernel(const int* __restrict__ text, float* __restrict__ outlen)
{
    __shared__ int sred[TT];
    int b = blockIdx.x, tid = threadIdx.x;
    sred[tid] = (text[b*TT+tid] != 0) ? 1 : 0;
    __syncthreads();
    for (int s=TT/2; s; s>>=1){
        if (tid < s) sred[tid] += sred[tid+s];
        __syncthreads();
    }
    if (tid==0){ g_lens[b] = sred[0]; outlen[b] = (float)sred[0]; }
}

// ---------------- CRF log-likelihood ----------------
__global__ void crf_ll_kernel(const float* __restrict__ logits, const int* __restrict__ labels,
                              const float* __restrict__ trans, float* __restrict__ outll)
{
    int b = blockIdx.x, lane = threadIdx.x;
    __shared__ float tr[LL*LL];
    for (int i=lane;i<LL*LL;i+=32) tr[i]=trans[i];
    __syncwarp();
    int len = g_lens[b];
    const float* lg = logits + (long)b*TT*LL;
    const int* lab = labels + b*TT;

    float un=0.f, bi=0.f;
    for (int t=lane;t<TT;t+=32){
        if (t < len)           un += lg[t*LL + lab[t]];
        if (t >= 1 && t < len) bi += tr[lab[t-1]*LL + lab[t]];
    }
    #pragma unroll
    for (int off=16;off;off>>=1){
        un += __shfl_down_sync(0xffffffffu, un, off);
        bi += __shfl_down_sync(0xffffffffu, bi, off);
    }

    int j = (lane<LL)? lane : 0;
    float alpha = (lane<LL)? lg[lane] : -1e30f;
    for (int t=1;t<TT;t++){
        float lt = (lane<LL)? lg[t*LL+lane] : 0.f;
        float av[LL]; float mx = -1e30f;
        #pragma unroll
        for (int i=0;i<LL;i++){
            float ai = __shfl_sync(0xffffffffu, alpha, i);
            av[i] = ai + tr[i*LL + j];
            mx = fmaxf(mx, av[i]);
        }
        float ssum = 0.f;
        #pragma unroll
        for (int i=0;i<LL;i++) ssum += expf(av[i]-mx);
        float nw = logf(ssum) + mx + lt;
        if (lane<LL && t<len) alpha = nw;
    }
    float mx2 = -1e30f;
    #pragma unroll
    for (int i=0;i<LL;i++) mx2 = fmaxf(mx2, __shfl_sync(0xffffffffu, alpha, i));
    float s2 = 0.f;
    #pragma unroll
    for (int i=0;i<LL;i++) s2 += expf(__shfl_sync(0xffffffffu, alpha, i) - mx2);
    float log_norm = logf(s2) + mx2;
    if (lane==0) outll[b] = un + bi - log_norm;
}

// ---------------- Viterbi decode ----------------
__global__ void viterbi_kernel(const float* __restrict__ logits, const float* __restrict__ trans,
                               float* __restrict__ outtags)
{
    int b = blockIdx.x, lane = threadIdx.x;
    __shared__ float tr[LL*LL];
    __shared__ unsigned char bp[TT-1][LL];
    for (int i=lane;i<LL*LL;i+=32) tr[i]=trans[i];
    __syncwarp();
    int len = g_lens[b];
    const float* lg = logits + (long)b*TT*LL;

    float alpha = (lane<LL)? lg[lane] : -1e30f;
    int j = (lane<LL)? lane : 0;
    for (int t=1;t<TT;t++){
        float lt = (lane<LL)? lg[t*LL+lane] : 0.f;
        float best = -1e30f; int bidx = 0;
        #pragma unroll
        for (int i=0;i<LL;i++){
            float v = __shfl_sync(0xffffffffu, alpha, i) + tr[i*LL + j];
            if (v > best){ best = v; bidx = i; }
        }
        if (lane<LL){
            bool m = (t < len);
            if (m) alpha = best + lt;
            bp[t-1][lane] = m ? (unsigned char)bidx : (unsigned char)lane;
        }
    }
    __syncwarp();
    int last = 0; float bv = -1e30f;
    #pragma unroll
    for (int i=0;i<LL;i++){
        float v = __shfl_sync(0xffffffffu, alpha, i);
        if (v > bv){ bv = v; last = i; }
    }
    if (lane==0){
        int tag = last;
        outtags[b*TT + TT-1] = (float)tag;
        for (int t=TT-2;t>=0;t--){
            tag = bp[t][tag];
            outtags[b*TT + t] = (float)tag;
        }
    }
}

// ---------------- launch ----------------
extern "C" void kernel_launch(void* const* d_in, const int* in_sizes, int n_in,
                              void* d_out, int out_size)
{
    const int*   text  = (const int*)  d_in[0];
    const int*   sent  = (const int*)  d_in[1];
    const int*   labels= (const int*)  d_in[2];
    const float* wemb  = (const float*)d_in[3];
    const float* semb  = (const float*)d_in[4];
    const float* Wk_f  = (const float*)d_in[5];
    const float* Wr_f  = (const float*)d_in[6];
    const float* b_f   = (const float*)d_in[7];
    const float* Wk_b  = (const float*)d_in[8];
    const float* Wr_b  = (const float*)d_in[9];
    const float* b_b   = (const float*)d_in[10];
    const float* Wd    = (const float*)d_in[11];
    const float* bd    = (const float*)d_in[12];
    const float* trans = (const float*)d_in[13];
    float* out = (float*)d_out;

    cudaFuncSetAttribute(lstm_persistent, cudaFuncAttributeMaxDynamicSharedMemorySize, LSTM_SMEM);

    embed_kernel<<<(MM*DD + 255)/256, 256>>>(text, sent, wemb, semb);
    gemm_xz_kernel<<<dim3(128, 64), 256>>>(Wk_f, b_f, Wk_b, b_b);
    lstm_persistent<<<128, 128, LSTM_SMEM>>>(Wr_f, Wr_b);
    logits_kernel<<<256, 64>>>(Wd, bd, out);
    lens_kernel<<<BB, TT>>>(text, out + LEN_OFF);
    crf_ll_kernel<<<BB, 32>>>(out, labels, trans, out + LLK_OFF);
    viterbi_kernel<<<BB, 32>>>(out, trans, out + TAG_OFF);
}

// round 7
// speedup vs baseline: 3.5379x; 1.8743x over previous
#include <cuda_runtime.h>
#include <cuda_bf16.h>
#include <math.h>

typedef unsigned long long u64;
typedef unsigned u32;

#define BB 64
#define TT 256
#define DD 600
#define HH 512
#define GG 2048
#define LL 9
#define MM (BB*TT)

#define LEN_OFF (MM*LL)
#define LLK_OFF (LEN_OFF + BB)
#define TAG_OFF (LLK_OFF + BB)

// -------- scratch (device globals) --------
__device__ float g_x[(size_t)MM*DD];
__device__ float g_xz[2][(size_t)MM*GG];
__device__ float g_hT[2][TT][HH][BB];                 // [dir][t][u][b] fp32 history
__device__ __align__(16) u32 g_hHi[2][2][BB][HH/2];   // [ph][dir][b][u-pair] bf16x2 hi
__device__ __align__(16) u32 g_hMid[2][2][BB][HH/2];  // bf16x2 mid
__device__ int g_lens[BB];
__device__ unsigned g_cnt2[2];

__device__ __forceinline__ float sigf(float x){ return 1.f/(1.f+__expf(-x)); }
__device__ __forceinline__ float tanhfast(float x){
    x = fminf(fmaxf(x, -15.f), 15.f);
    float e = __expf(2.f*x);
    return (e-1.f)/(e+1.f);
}
__device__ __forceinline__ unsigned f2tf(float f){
    unsigned r; asm("cvt.rna.tf32.f32 %0,%1;" : "=r"(r) : "f"(f)); return r;
}
__device__ __forceinline__ void mma8(float* d, const unsigned* a, const unsigned* b){
    asm("mma.sync.aligned.m16n8k8.row.col.f32.tf32.tf32.f32 "
        "{%0,%1,%2,%3},{%4,%5,%6,%7},{%8,%9},{%0,%1,%2,%3};"
        : "+f"(d[0]),"+f"(d[1]),"+f"(d[2]),"+f"(d[3])
        : "r"(a[0]),"r"(a[1]),"r"(a[2]),"r"(a[3]),"r"(b[0]),"r"(b[1]));
}
__device__ __forceinline__ void mma16(float* d, const unsigned* a, const unsigned* b){
    asm("mma.sync.aligned.m16n8k16.row.col.f32.bf16.bf16.f32 "
        "{%0,%1,%2,%3},{%4,%5,%6,%7},{%8,%9},{%0,%1,%2,%3};"
        : "+f"(d[0]),"+f"(d[1]),"+f"(d[2]),"+f"(d[3])
        : "r"(a[0]),"r"(a[1]),"r"(a[2]),"r"(a[3]),"r"(b[0]),"r"(b[1]));
}
// split float into bf16 hi/mid parts
__device__ __forceinline__ void bfsplit(float w, unsigned short& hi, unsigned short& mid){
    __nv_bfloat16 h = __float2bfloat16_rn(w);
    float r = w - __bfloat162float(h);
    __nv_bfloat16 m = __float2bfloat16_rn(r);
    hi = __bfloat16_as_ushort(h); mid = __bfloat16_as_ushort(m);
}

// ---------------- embedding gather ----------------
__global__ void embed_kernel(const int* __restrict__ text, const int* __restrict__ sent,
                             const float* __restrict__ wemb, const float* __restrict__ semb)
{
    int idx = blockIdx.x*blockDim.x + threadIdx.x;
    if (idx == 0){ g_cnt2[0] = 0; g_cnt2[1] = 0; }
    if (idx >= MM*DD) return;
    int e = idx % DD, bt = idx / DD;
    g_x[idx] = (e < 300) ? wemb[(long)text[bt]*300 + e] : semb[(long)sent[bt]*300 + (e-300)];
}

// ---------------- xz = x @ Wk + b  (TF32 mma.sync, double-buffered) ----------------
#define AST 28
#define WST 72
__global__ void __launch_bounds__(256,2) gemm_xz_kernel(const float* __restrict__ Wk_f, const float* __restrict__ b_f,
                                                        const float* __restrict__ Wk_b, const float* __restrict__ b_b)
{
    __shared__ unsigned As[2][128*AST];
    __shared__ unsigned Ws[2][24*WST];

    int tid = threadIdx.x;
    int warp = tid>>5, lane = tid&31;
    int g = lane>>2, tig = lane&3;
    int m0g = blockIdx.x*128;
    int nb  = blockIdx.y;
    const float* Bmat = (nb>=32)? Wk_b : Wk_f;
    const float* bias = (nb>=32)? b_b  : b_f;
    float* C = (nb>=32)? g_xz[1] : g_xz[0];
    int n0g = (nb&31)*64;
    int wm = (warp>>1)*32;
    int wn = (warp&1)*32;

    float acc[2][4][4];
    #pragma unroll
    for (int mt=0;mt<2;mt++)
        #pragma unroll
        for (int nt=0;nt<4;nt++)
            #pragma unroll
            for (int r=0;r<4;r++) acc[mt][nt][r]=0.f;

    int arow = tid>>1, acb = (tid&1)*12;
    int wi0 = tid*2;

    float4 pa[3], pw[2];
    #pragma unroll
    for (int j=0;j<3;j++)
        pa[j] = *(const float4*)&g_x[(long)(m0g+arow)*DD + acb + 4*j];
    if (tid < 192){
        #pragma unroll
        for (int q=0;q<2;q++){
            int i = wi0+q; int k = i>>4, nq = i&15;
            pw[q] = *(const float4*)&Bmat[(long)k*GG + n0g + nq*4];
        }
    }
    #pragma unroll
    for (int j=0;j<3;j++){
        unsigned* d = &As[0][arow*AST + acb + 4*j];
        d[0]=f2tf(pa[j].x); d[1]=f2tf(pa[j].y); d[2]=f2tf(pa[j].z); d[3]=f2tf(pa[j].w);
    }
    if (tid < 192){
        #pragma unroll
        for (int q=0;q<2;q++){
            int i = wi0+q; int k = i>>4, nq = i&15;
            unsigned* d = &Ws[0][k*WST + nq*4];
            d[0]=f2tf(pw[q].x); d[1]=f2tf(pw[q].y); d[2]=f2tf(pw[q].z); d[3]=f2tf(pw[q].w);
        }
    }
    __syncthreads();

    for (int ch=0; ch<25; ch++){
        int cur = ch&1;
        if (ch < 24){
            int kb = (ch+1)*24;
            #pragma unroll
            for (int j=0;j<3;j++)
                pa[j] = *(const float4*)&g_x[(long)(m0g+arow)*DD + kb + acb + 4*j];
            if (tid < 192){
                #pragma unroll
                for (int q=0;q<2;q++){
                    int i = wi0+q; int k = i>>4, nq = i&15;
                    pw[q] = *(const float4*)&Bmat[(long)(kb+k)*GG + n0g + nq*4];
                }
            }
        }
        const unsigned* Ab = &As[cur][0];
        const unsigned* Wb = &Ws[cur][0];
        #pragma unroll
        for (int ks=0;ks<3;ks++){
            int kb = ks*8;
            unsigned a[2][4], b[4][2];
            #pragma unroll
            for (int mt=0;mt<2;mt++){
                int r0 = wm + mt*16;
                a[mt][0] = Ab[(r0+g  )*AST + kb+tig  ];
                a[mt][1] = Ab[(r0+g+8)*AST + kb+tig  ];
                a[mt][2] = Ab[(r0+g  )*AST + kb+tig+4];
                a[mt][3] = Ab[(r0+g+8)*AST + kb+tig+4];
            }
            #pragma unroll
            for (int nt=0;nt<4;nt++){
                int c0 = wn + nt*8 + g;
                b[nt][0] = Wb[(kb+tig  )*WST + c0];
                b[nt][1] = Wb[(kb+tig+4)*WST + c0];
            }
            #pragma unroll
            for (int mt=0;mt<2;mt++)
                #pragma unroll
                for (int nt=0;nt<4;nt++)
                    mma8(acc[mt][nt], a[mt], b[nt]);
        }
        if (ch < 24){
            int nxt = (ch+1)&1;
            #pragma unroll
            for (int j=0;j<3;j++){
                unsigned* d = &As[nxt][arow*AST + acb + 4*j];
                d[0]=f2tf(pa[j].x); d[1]=f2tf(pa[j].y); d[2]=f2tf(pa[j].z); d[3]=f2tf(pa[j].w);
            }
            if (tid < 192){
                #pragma unroll
                for (int q=0;q<2;q++){
                    int i = wi0+q; int k = i>>4, nq = i&15;
                    unsigned* d = &Ws[nxt][k*WST + nq*4];
                    d[0]=f2tf(pw[q].x); d[1]=f2tf(pw[q].y); d[2]=f2tf(pw[q].z); d[3]=f2tf(pw[q].w);
                }
            }
        }
        __syncthreads();
    }

    #pragma unroll
    for (int mt=0;mt<2;mt++){
        int row0 = m0g + wm + mt*16 + g;
        #pragma unroll
        for (int nt=0;nt<4;nt++){
            int col = n0g + wn + nt*8 + 2*tig;
            float b0 = bias[col], b1 = bias[col+1];
            float2 o0 = {acc[mt][nt][0]+b0, acc[mt][nt][1]+b1};
            float2 o1 = {acc[mt][nt][2]+b0, acc[mt][nt][3]+b1};
            *(float2*)&C[(long)row0*GG + col]     = o0;
            *(float2*)&C[(long)(row0+8)*GG + col] = o1;
        }
    }
}

// ---------------- persistent bidirectional LSTM (bf16 hi/mid 3-pass mma) ----------------
// 128 blocks (dir, bh, cg) x 128 thr. Block: M=32 batch (b0..b0+31), N=64 cols (units u0..u0+15 x 4 gates), K=512.
// smem: Whi/Wmid [64n][260 u32-pairs] + Ahi/Amid [32m][260]
#define LSW (64*260)
#define LSA (32*260)
#define LSTM_SMEM ((2*LSW + 2*LSA)*4)
__global__ void __launch_bounds__(128,1) lstm_persistent(const float* __restrict__ Wr_f,
                                                         const float* __restrict__ Wr_b)
{
    extern __shared__ u32 sm[];
    u32 *WHs = sm, *WMs = sm + LSW, *AHs = sm + 2*LSW, *AMs = sm + 2*LSW + LSA;

    int tid = threadIdx.x, bid = blockIdx.x;
    int dir = bid>>6, rr = bid&63, bh = rr>>5, cg = rr&31;
    int b0 = bh*32, u0 = cg*16;
    const float* Wr = dir ? Wr_b : Wr_f;
    const float* xz = g_xz[dir];

    // stage W hi/mid: [n][kk], n = gate*16+unit, kk = k-pair
    for (int i = tid; i < 64*256; i += 128){
        int n = i&63, kk = i>>6;
        int col = (n>>4)*HH + u0 + (n&15);
        float w0 = Wr[(long)(2*kk)*GG + col];
        float w1 = Wr[(long)(2*kk+1)*GG + col];
        unsigned short h0,m0,h1,m1;
        bfsplit(w0,h0,m0); bfsplit(w1,h1,m1);
        WHs[n*260+kk] = ((u32)h1<<16) | h0;
        WMs[n*260+kk] = ((u32)m1<<16) | m0;
    }

    int lane = tid&31, w = tid>>5;
    int g = lane>>2, tig = lane&3;
    int mt = w>>1, uh = w&1;
    float cst[4] = {0.f,0.f,0.f,0.f};   // [bi*2+j]
    __syncthreads();

    for (int s=0; s<TT; s++){
        int t = dir ? (TT-1-s) : s;
        int ph = s&1;

        // prefetch xz addends: [q][bi] float2 (cols 2tig,2tig+1)
        float2 pz[4][2];
        #pragma unroll
        for (int q=0;q<4;q++)
            #pragma unroll
            for (int bi=0;bi<2;bi++){
                int brow = b0 + mt*16 + g + bi*8;
                pz[q][bi] = *(const float2*)&xz[((long)brow*TT + t)*GG + q*HH + u0 + uh*8 + 2*tig];
            }

        float acc[4][4];
        #pragma unroll
        for (int q=0;q<4;q++)
            #pragma unroll
            for (int r=0;r<4;r++) acc[q][r]=0.f;

        if (s){
            int php = (s-1)&1;
            const uint4* srcH = (const uint4*)&g_hHi[php][dir][b0][0];
            const uint4* srcM = (const uint4*)&g_hMid[php][dir][b0][0];
            #pragma unroll
            for (int j=0;j<16;j++){
                int idx = j*128 + tid;
                int m = idx>>6, qq = idx&63;
                uint4 vh = __ldcg(&srcH[m*64 + qq]);
                uint4 vm = __ldcg(&srcM[m*64 + qq]);
                *(uint4*)&AHs[m*260 + qq*4] = vh;
                *(uint4*)&AMs[m*260 + qq*4] = vm;
            }
            __syncthreads();

            int ar  = (mt*16 + g)*260;
            int ar8 = (mt*16 + 8 + g)*260;
            #pragma unroll 4
            for (int kt=0;kt<32;kt++){
                int kb = kt*8;
                unsigned ah[4], am[4];
                ah[0]=AHs[ar +kb+tig]; ah[1]=AHs[ar8+kb+tig];
                ah[2]=AHs[ar +kb+4+tig]; ah[3]=AHs[ar8+kb+4+tig];
                am[0]=AMs[ar +kb+tig]; am[1]=AMs[ar8+kb+tig];
                am[2]=AMs[ar +kb+4+tig]; am[3]=AMs[ar8+kb+4+tig];
                #pragma unroll
                for (int q=0;q<4;q++){
                    int c = (q*16 + uh*8 + g)*260;
                    unsigned bhv[2] = {WHs[c+kb+tig], WHs[c+kb+4+tig]};
                    unsigned bmv[2] = {WMs[c+kb+tig], WMs[c+kb+4+tig]};
                    mma16(acc[q], ah, bhv);
                    mma16(acc[q], ah, bmv);
                    mma16(acc[q], am, bhv);
                }
            }
        }

        // gates + state update; acc[q]: c0=(bi0,j0) c1=(bi0,j1) c2=(bi1,j0) c3=(bi1,j1)
        #pragma unroll
        for (int bi=0;bi<2;bi++){
            int brow = b0 + mt*16 + g + bi*8;
            float zi0 = acc[0][bi*2  ] + pz[0][bi].x;
            float zi1 = acc[0][bi*2+1] + pz[0][bi].y;
            float zf0 = acc[1][bi*2  ] + pz[1][bi].x;
            float zf1 = acc[1][bi*2+1] + pz[1][bi].y;
            float zg0 = acc[2][bi*2  ] + pz[2][bi].x;
            float zg1 = acc[2][bi*2+1] + pz[2][bi].y;
            float zo0 = acc[3][bi*2  ] + pz[3][bi].x;
            float zo1 = acc[3][bi*2+1] + pz[3][bi].y;
            float cn0 = sigf(zf0)*cst[bi*2  ] + sigf(zi0)*tanhfast(zg0);
            float cn1 = sigf(zf1)*cst[bi*2+1] + sigf(zi1)*tanhfast(zg1);
            cst[bi*2  ] = cn0; cst[bi*2+1] = cn1;
            float h0 = sigf(zo0)*tanhfast(cn0);
            float h1 = sigf(zo1)*tanhfast(cn1);
            unsigned short hh0,hm0,hh1,hm1;
            bfsplit(h0,hh0,hm0); bfsplit(h1,hh1,hm1);
            int up = cg*8 + uh*4 + tig;
            g_hHi [ph][dir][brow][up] = ((u32)hh1<<16) | hh0;
            g_hMid[ph][dir][brow][up] = ((u32)hm1<<16) | hm0;
            int ug = u0 + uh*8 + 2*tig;
            g_hT[dir][t][ug  ][brow] = h0;
            g_hT[dir][t][ug+1][brow] = h1;
        }

        if (s < TT-1){
            __threadfence();
            __syncthreads();
            if (tid==0){
                atomicAdd(&g_cnt2[dir], 1u);
                unsigned tgt = 64u*(unsigned)(s+1);
                while (*(volatile unsigned*)&g_cnt2[dir] < tgt) __nanosleep(32);
            }
            __syncthreads();
        }
    }
}

// ---------------- logits = [hf|hb] @ Wd + bd ----------------
// grid 256 (one t per block), 256 thr: (b, k-quarter), smem reduce
__global__ void logits_kernel(const float* __restrict__ Wd, const float* __restrict__ bd,
                              float* __restrict__ out)
{
    __shared__ float sacc[4][BB][LL];
    int t = blockIdx.x, tid = threadIdx.x;
    int b = tid&63, uq = tid>>6;
    int dirsel = uq>>1, ub = (uq&1)*256;
    float acc[LL];
    #pragma unroll
    for (int l=0;l<LL;l++) acc[l]=0.f;
    const float* hp = &g_hT[dirsel][t][ub][0];
    const float* wp = &Wd[(dirsel*HH + ub)*LL];
    for (int j=0;j<256;j++){
        float v = hp[j*BB + b];
        #pragma unroll
        for (int l=0;l<LL;l++) acc[l] += v * __ldg(&wp[j*LL + l]);
    }
    #pragma unroll
    for (int l=0;l<LL;l++) sacc[uq][b][l] = acc[l];
    __syncthreads();
    for (int i=tid; i<BB*LL; i+=256){
        int bb = i/LL, l = i%LL;
        float v = sacc[0][bb][l]+sacc[1][bb][l]+sacc[2][bb][l]+sacc[3][bb][l] + bd[l];
        out[((long)bb*TT + t)*LL + l] = v;
    }
}

// ---------------- text lens ----------------
__global__ void lens_kernel(const int* __restrict__ text, float* __restrict__ outlen)
{
    __shared__ int sred[TT];
    int b = blockIdx.x, tid = threadIdx.x;
    sred[tid] = (text[b*TT+tid] != 0) ? 1 : 0;
    __syncthreads();
    for (int s=TT/2; s; s>>=1){
        if (tid < s) sred[tid] += sred[tid+s];
        __syncthreads();
    }
    if (tid==0){ g_lens[b] = sred[0]; outlen[b] = (float)sred[0]; }
}

// ---------------- CRF log-likelihood ----------------
__global__ void crf_ll_kernel(const float* __restrict__ logits, const int* __restrict__ labels,
                              const float* __restrict__ trans, float* __restrict__ outll)
{
    int b = blockIdx.x, lane = threadIdx.x;
    __shared__ float tr[LL*LL];
    for (int i=lane;i<LL*LL;i+=32) tr[i]=trans[i];
    __syncwarp();
    int len = g_lens[b];
    const float* lg = logits + (long)b*TT*LL;
    const int* lab = labels + b*TT;

    float un=0.f, bi=0.f;
    for (int t=lane;t<TT;t+=32){
        if (t < len)           un += lg[t*LL + lab[t]];
        if (t >= 1 && t < len) bi += tr[lab[t-1]*LL + lab[t]];
    }
    #pragma unroll
    for (int off=16;off;off>>=1){
        un += __shfl_down_sync(0xffffffffu, un, off);
        bi += __shfl_down_sync(0xffffffffu, bi, off);
    }

    int j = (lane<LL)? lane : 0;
    float alpha = (lane<LL)? lg[lane] : -1e30f;
    for (int t=1;t<TT;t++){
        float lt = (lane<LL)? lg[t*LL+lane] : 0.f;
        float av[LL]; float mx = -1e30f;
        #pragma unroll
        for (int i=0;i<LL;i++){
            float ai = __shfl_sync(0xffffffffu, alpha, i);
            av[i] = ai + tr[i*LL + j];
            mx = fmaxf(mx, av[i]);
        }
        float ssum = 0.f;
        #pragma unroll
        for (int i=0;i<LL;i++) ssum += expf(av[i]-mx);
        float nw = logf(ssum) + mx + lt;
        if (lane<LL && t<len) alpha = nw;
    }
    float mx2 = -1e30f;
    #pragma unroll
    for (int i=0;i<LL;i++) mx2 = fmaxf(mx2, __shfl_sync(0xffffffffu, alpha, i));
    float s2 = 0.f;
    #pragma unroll
    for (int i=0;i<LL;i++) s2 += expf(__shfl_sync(0xffffffffu, alpha, i) - mx2);
    float log_norm = logf(s2) + mx2;
    if (lane==0) outll[b] = un + bi - log_norm;
}

// ---------------- Viterbi decode ----------------
__global__ void viterbi_kernel(const float* __restrict__ logits, const float* __restrict__ trans,
                               float* __restrict__ outtags)
{
    int b = blockIdx.x, lane = threadIdx.x;
    __shared__ float tr[LL*LL];
    __shared__ unsigned char bp[TT-1][LL];
    for (int i=lane;i<LL*LL;i+=32) tr[i]=trans[i];
    __syncwarp();
    int len = g_lens[b];
    const float* lg = logits + (long)b*TT*LL;

    float alpha = (lane<LL)? lg[lane] : -1e30f;
    int j = (lane<LL)? lane : 0;
    for (int t=1;t<TT;t++){
        float lt = (lane<LL)? lg[t*LL+lane] : 0.f;
        float best = -1e30f; int bidx = 0;
        #pragma unroll
        for (int i=0;i<LL;i++){
            float v = __shfl_sync(0xffffffffu, alpha, i) + tr[i*LL + j];
            if (v > best){ best = v; bidx = i; }
        }
        if (lane<LL){
            bool m = (t < len);
            if (m) alpha = best + lt;
            bp[t-1][lane] = m ? (unsigned char)bidx : (unsigned char)lane;
        }
    }
    __syncwarp();
    int last = 0; float bv = -1e30f;
    #pragma unroll
    for (int i=0;i<LL;i++){
        float v = __shfl_sync(0xffffffffu, alpha, i);
        if (v > bv){ bv = v; last = i; }
    }
    if (lane==0){
        int tag = last;
        outtags[b*TT + TT-1] = (float)tag;
        for (int t=TT-2;t>=0;t--){
            tag = bp[t][tag];
            outtags[b*TT + t] = (float)tag;
        }
    }
}

// ---------------- launch ----------------
extern "C" void kernel_launch(void* const* d_in, const int* in_sizes, int n_in,
                              void* d_out, int out_size)
{
    const int*   text  = (const int*)  d_in[0];
    const int*   sent  = (const int*)  d_in[1];
    const int*   labels= (const int*)  d_in[2];
    const float* wemb  = (const float*)d_in[3];
    const float* semb  = (const float*)d_in[4];
    const float* Wk_f  = (const float*)d_in[5];
    const float* Wr_f  = (const float*)d_in[6];
    const float* b_f   = (const float*)d_in[7];
    const float* Wk_b  = (const float*)d_in[8];
    const float* Wr_b  = (const float*)d_in[9];
    const float* b_b   = (const float*)d_in[10];
    const float* Wd    = (const float*)d_in[11];
    const float* bd    = (const float*)d_in[12];
    const float* trans = (const float*)d_in[13];
    float* out = (float*)d_out;

    cudaFuncSetAttribute(lstm_persistent, cudaFuncAttributeMaxDynamicSharedMemorySize, LSTM_SMEM);

    embed_kernel<<<(MM*DD + 255)/256, 256>>>(text, sent, wemb, semb);
    gemm_xz_kernel<<<dim3(128, 64), 256>>>(Wk_f, b_f, Wk_b, b_b);
    lstm_persistent<<<128, 128, LSTM_SMEM>>>(Wr_f, Wr_b);
    logits_kernel<<<256, 256>>>(Wd, bd, out);
    lens_kernel<<<BB, TT>>>(text, out + LEN_OFF);
    crf_ll_kernel<<<BB, 32>>>(out, labels, trans, out + LLK_OFF);
    viterbi_kernel<<<BB, 32>>>(out, trans, out + TAG_OFF);
}